// round 17
// baseline (speedup 1.0000x reference)
#include <cuda_runtime.h>
#include <cuda_fp16.h>
#include <cstdint>

#define BSZ 32
#define CNT 128
#define Wd  2048
#define Pd  1024
#define Ed  8
#define Kc  25
#define Ld  2
#define ROWS (BSZ*CNT)   // 4096
#define NSLOTS 296       // 148 SMs x 2 CTAs

// ---------------- scratch ----------------
__device__ float  g_x[ROWS*Wd];
__device__ __half g_ch[ROWS*Wd];
__device__ __half g_cm[ROWS*Wd];
__device__ float  g_qkv[3*ROWS*Pd];
__device__ __half g_ph[ROWS*Pd];
__device__ __half g_pm[ROWS*Pd];
__device__ __half g_wqkv[3*Ld*Pd*Wd];
__device__ __half g_wo[Ld*Wd*Pd];
__device__ float  g_bqkv[3*Ld*Pd];
__device__ float  g_wavg[Ld*Kc];
__device__ float  g_bavg[Ld];

// ---------------- helpers ----------------
__device__ __forceinline__ uint32_t smem_u32(const void* p) {
    uint32_t a;
    asm("{ .reg .u64 t; cvta.to.shared.u64 t, %1; cvt.u32.u64 %0, t; }" : "=r"(a) : "l"(p));
    return a;
}
__device__ __forceinline__ void cp16(uint32_t dst, const void* src) {
    asm volatile("cp.async.cg.shared.global [%0], [%1], 16;" :: "r"(dst), "l"(src));
}
__device__ __forceinline__ void split2h(float x, __half& h, __half& m) {
    h = __float2half(x);
    m = __float2half(x - __half2float(h));
}
__device__ __forceinline__ uint32_t pack2h(__half a, __half b) {
    return (uint32_t)__half_as_ushort(a) | ((uint32_t)__half_as_ushort(b) << 16);
}
__device__ __forceinline__ float2 cmulf(float2 a, float2 b) {
    return make_float2(a.x * b.x - a.y * b.y, a.x * b.y + a.y * b.x);
}

// ---------------- weight convert fp32 -> fp16 (all 4 matrices, one launch) ----------------
__global__ void cvt16_all_kernel(const float* __restrict__ wq, const float* __restrict__ wk,
                                 const float* __restrict__ wv, const float* __restrict__ wo,
                                 __half* __restrict__ wqkv, __half* __restrict__ wod, int n8) {
    int i = blockIdx.x * blockDim.x + threadIdx.x;
    int stride = gridDim.x * blockDim.x;
    for (; i < 4 * n8; i += stride) {
        int sel = i / n8, j = i - sel * n8;
        const float* src = (sel == 0) ? wq : (sel == 1) ? wk : (sel == 2) ? wv : wo;
        __half* dst = (sel < 3) ? (wqkv + (size_t)sel * n8 * 8) : wod;
        float4 v0 = ((const float4*)src)[2 * j];
        float4 v1 = ((const float4*)src)[2 * j + 1];
        uint4 u;
        u.x = pack2h(__float2half(v0.x), __float2half(v0.y));
        u.y = pack2h(__float2half(v0.z), __float2half(v0.w));
        u.z = pack2h(__float2half(v1.x), __float2half(v1.y));
        u.w = pack2h(__float2half(v1.z), __float2half(v1.w));
        ((uint4*)dst)[j] = u;
    }
}

// ---------------- avg conv weights ----------------
__global__ void avg_conv_kernel(const float* __restrict__ cw, const float* __restrict__ cb,
                                float* __restrict__ wavg, float* __restrict__ bavg) {
    int idx = threadIdx.x;
    if (idx < Ld * Kc) {
        int l = idx / Kc, kk = idx % Kc;
        float s = 0.f;
        #pragma unroll
        for (int e = 0; e < Ed; e++) s += cw[(l * Ed + e) * Kc + kk];
        wavg[idx] = s * (1.0f / Ed);
    }
    if (idx < Ld) {
        float s = 0.f;
        #pragma unroll
        for (int e = 0; e < Ed; e++) s += cb[idx * Ed + e];
        bavg[idx] = s * (1.0f / Ed);
    }
}

// ---------------- 1D conv, writes fp16 h/m ----------------
__global__ __launch_bounds__(256) void conv_row_kernel(
    const float* __restrict__ X, __half* __restrict__ Yh, __half* __restrict__ Ym,
    const float* __restrict__ wavg, const float* __restrict__ bavg)
{
    __shared__ float sx[Wd + Kc - 1];
    __shared__ float wsh[Kc];
    const int row = blockIdx.x;
    const int tid = threadIdx.x;
    const float* xr = X + (size_t)row * Wd;

    for (int i = tid; i < Wd + Kc - 1; i += 256) {
        int src = i - (Kc / 2);
        sx[i] = (src >= 0 && src < Wd) ? xr[src] : 0.0f;
    }
    if (tid < Kc) wsh[tid] = wavg[tid];
    __syncthreads();

    const float b = bavg[0];
    __half* yh = Yh + (size_t)row * Wd;
    __half* ym = Ym + (size_t)row * Wd;
    for (int h = tid; h < Wd; h += 256) {
        float s = b;
        #pragma unroll
        for (int k = 0; k < Kc; k++) s += sx[h + k] * wsh[k];
        __half sh, sm_;
        split2h(s, sh, sm_);
        yh[h] = sh; ym[h] = sm_;
    }
}

// ---------------- fp16x2 mma.sync GEMM, BK=64, persistent grid ----------------
#define MMA16(cc, aa, bb) \
    asm volatile("mma.sync.aligned.m16n8k16.row.col.f32.f16.f16.f32 " \
        "{%0,%1,%2,%3},{%4,%5,%6,%7},{%8,%9},{%0,%1,%2,%3};" \
        : "+f"((cc)[0]), "+f"((cc)[1]), "+f"((cc)[2]), "+f"((cc)[3]) \
        : "r"((aa)[0]), "r"((aa)[1]), "r"((aa)[2]), "r"((aa)[3]), \
          "r"((bb)[0]), "r"((bb)[1]))

#define LDMX4(r0, r1, r2, r3, a) \
    asm volatile("ldmatrix.sync.aligned.m8n8.x4.shared.b16 {%0,%1,%2,%3}, [%4];" \
        : "=r"(r0), "=r"(r1), "=r"(r2), "=r"(r3) : "r"(a))

#define BK 64
#define TILE_B 16384           // 128 rows x 128 bytes (64 fp16), swizzled
#define STAGE_B (3*TILE_B)     // Ah, Am, W = 48KB
#define GEMM_SMEM (2*STAGE_B)  // 98304 bytes

__global__ __launch_bounds__(256, 2) void gemm_mma_kernel(
    const __half* __restrict__ Ah, const __half* __restrict__ Am,
    const __half* __restrict__ Bw,
    const float* __restrict__ bias, float* __restrict__ C,
    int Kd, int N, size_t szB, size_t szBias, size_t szC,
    int ntN, int ntTiles)   // tiles per z = ntN*32; total tiles = ntTiles
{
    extern __shared__ uint32_t sm[];
    const uint32_t sbase = smem_u32(sm);

    const int tid = threadIdx.x;
    const int wid = tid >> 5, lane = tid & 31;
    const int g = lane >> 2, t = lane & 3;
    const int wm = (wid >> 1) * 32;
    const int wn = (wid & 1) * 64;
    const int stA = wid & 1;

    // ---- per-lane fragment offsets (tile-relative; constant across tiles) ----
    const int lr = lane & 7;
    const int ls = lane >> 3;
    uint32_t Abase[4], Bbase[4];
    #pragma unroll
    for (int st = 0; st < 4; st++) {
        int arow = wm + lr + (ls & 1) * 8;
        int agrp = st * 2 + (ls >> 1);
        Abase[st] = (uint32_t)(arow * 128 + ((agrp ^ (arow & 7)) << 4));
        int brow = wn + (ls >> 1) * 8 + lr;
        int bgrp = st * 2 + (ls & 1);
        Bbase[st] = (uint32_t)(brow * 128 + ((bgrp ^ (brow & 7)) << 4));
    }

    // cp.async destination offsets (tile-relative)
    const int crow = tid >> 3;
    const int cg = tid & 7;
    const uint32_t sg = (uint32_t)(cg ^ (crow & 7));
    uint32_t cdst[4];
    #pragma unroll
    for (int j = 0; j < 4; j++)
        cdst[j] = (uint32_t)((crow + j * 32) * 128) + (sg << 4);

    const size_t rstep = (size_t)32 * Kd;
    const int NC = Kd / BK;
    const int ntZ = ntN * 32;      // tiles per z slice (ntM = 32 fixed)

    for (int tile = blockIdx.x; tile < ntTiles; tile += NSLOTS) {
        const int z  = tile / ntZ;
        const int r  = tile - z * ntZ;
        const int by = r / ntN;
        const int bx = r - by * ntN;
        const int bm = by * 128, bn = bx * 128;

        const __half* pAh = Ah + (size_t)(bm + crow) * Kd + cg * 8;
        const __half* pAm = Am + (size_t)(bm + crow) * Kd + cg * 8;
        const __half* pBw = Bw + (size_t)z * szB + (size_t)(bn + crow) * Kd + cg * 8;

        float acc[2][8][4];
        #pragma unroll
        for (int mt = 0; mt < 2; mt++)
            #pragma unroll
            for (int nt = 0; nt < 8; nt++)
                #pragma unroll
                for (int e = 0; e < 4; e++) acc[mt][nt][e] = 0.0f;

        #define ISSUE(s, kpos) do { \
            uint32_t _sb = sbase + (uint32_t)(s) * STAGE_B; \
            _Pragma("unroll") \
            for (int j = 0; j < 4; j++) { \
                cp16(_sb + cdst[j],              pAh + j * rstep + (kpos)); \
                cp16(_sb + TILE_B + cdst[j],     pAm + j * rstep + (kpos)); \
                cp16(_sb + 2 * TILE_B + cdst[j], pBw + j * rstep + (kpos)); \
            } \
            asm volatile("cp.async.commit_group;" ::: "memory"); \
        } while (0)

        ISSUE(0, 0);

        for (int i = 0; i < NC; i++) {
            asm volatile("cp.async.wait_group 0;" ::: "memory");
            __syncthreads();
            if (i + 1 < NC) ISSUE((i + 1) & 1, (i + 1) * BK);

            const uint32_t sAh = sbase + (uint32_t)(i & 1) * STAGE_B;
            const uint32_t sAm = sAh + TILE_B;
            const uint32_t sBw = sAm + TILE_B;

            #pragma unroll
            for (int s = 0; s < 4; s++) {
                const int st = s ^ stA;
                const uint32_t ab = Abase[st];
                const uint32_t bb = Bbase[st];

                uint32_t bw[8][2];
                LDMX4(bw[0][0], bw[0][1], bw[1][0], bw[1][1], sBw + bb);
                LDMX4(bw[2][0], bw[2][1], bw[3][0], bw[3][1], sBw + bb + 2048);
                LDMX4(bw[4][0], bw[4][1], bw[5][0], bw[5][1], sBw + bb + 4096);
                LDMX4(bw[6][0], bw[6][1], bw[7][0], bw[7][1], sBw + bb + 6144);

                #pragma unroll
                for (int mt = 0; mt < 2; mt++) {
                    uint32_t ah[4], am_[4];
                    uint32_t ao = ab + (uint32_t)mt * 2048;
                    LDMX4(ah[0], ah[1], ah[2], ah[3], sAh + ao);
                    LDMX4(am_[0], am_[1], am_[2], am_[3], sAm + ao);
                    #pragma unroll
                    for (int nt = 0; nt < 8; nt++) {
                        MMA16(acc[mt][nt], ah,  bw[nt]);
                        MMA16(acc[mt][nt], am_, bw[nt]);
                    }
                }
            }
        }
        #undef ISSUE

        const float* bz = bias + (size_t)z * szBias;
        float* Cz = C + (size_t)z * szC;
        #pragma unroll
        for (int mt = 0; mt < 2; mt++) {
            #pragma unroll
            for (int nt = 0; nt < 8; nt++) {
                int col = bn + wn + nt * 8 + 2 * t;
                float b0 = __ldg(&bz[col]);
                float b1 = __ldg(&bz[col + 1]);
                float* p0 = Cz + (size_t)(bm + wm + mt * 16 + g) * N + col;
                float2 o0 = make_float2(acc[mt][nt][0] + b0, acc[mt][nt][1] + b1);
                float2 o1 = make_float2(acc[mt][nt][2] + b0, acc[mt][nt][3] + b1);
                *(float2*)p0 = o0;
                *(float2*)(p0 + 8 * N) = o1;
            }
        }
        // no barrier needed: next tile's ISSUE(0) touches stage 0, last read
        // before the final in-loop barrier of this tile.
    }
}

// ---------------- radix-4 FFT attention, 2 rows per block ----------------
__device__ __forceinline__ int rev4(int v) {
    return ((v & 3) << 8) | (((v >> 2) & 3) << 6) | (((v >> 4) & 3) << 4)
         | (((v >> 6) & 3) << 2) | ((v >> 8) & 3);
}

__device__ __forceinline__ void fft1024_r4(float2* s, const float2* Tw, int tid, bool inv) {
    #pragma unroll
    for (int stage = 0; stage < 5; ++stage) {
        const int q = 1 << (2 * stage);
        const int j = tid & (q - 1);
        const int grp = tid >> (2 * stage);
        const int i0 = grp * (q << 2) + j;
        const int i1 = i0 + q, i2 = i1 + q, i3 = i2 + q;

        float2 w1 = Tw[j << (8 - 2 * stage)];
        if (inv) w1.y = -w1.y;
        float2 w2 = cmulf(w1, w1);
        float2 w3 = cmulf(w1, w2);

        float2 a = s[i0];
        float2 b = cmulf(s[i1], w1);
        float2 c = cmulf(s[i2], w2);
        float2 d = cmulf(s[i3], w3);

        float2 acp = make_float2(a.x + c.x, a.y + c.y);
        float2 acm = make_float2(a.x - c.x, a.y - c.y);
        float2 bdp = make_float2(b.x + d.x, b.y + d.y);
        float2 bdm = make_float2(b.x - d.x, b.y - d.y);
        float2 ib = inv ? make_float2(-bdm.y, bdm.x) : make_float2(bdm.y, -bdm.x);

        s[i0] = make_float2(acp.x + bdp.x, acp.y + bdp.y);
        s[i1] = make_float2(acm.x + ib.x,  acm.y + ib.y);
        s[i2] = make_float2(acp.x - bdp.x, acp.y - bdp.y);
        s[i3] = make_float2(acm.x - ib.x,  acm.y - ib.y);
        __syncthreads();
    }
}

__global__ __launch_bounds__(256) void fft_attn_kernel(
    const float* __restrict__ Q, const float* __restrict__ Kx,
    const float* __restrict__ V,
    __half* __restrict__ Oh, __half* __restrict__ Om)
{
    __shared__ float2 Z[1024];
    __shared__ float2 A0[1024];
    __shared__ float2 A1[1024];
    __shared__ float2 Tw[256];
    const int row0 = blockIdx.x * 2;
    const int row1 = row0 + 1;
    const int tid = threadIdx.x;
    const float* q0 = Q  + (size_t)row0 * Pd;
    const float* k0 = Kx + (size_t)row0 * Pd;
    const float* q1 = Q  + (size_t)row1 * Pd;
    const float* k1 = Kx + (size_t)row1 * Pd;
    const float* v0 = V  + (size_t)row0 * Pd;
    const float* v1 = V  + (size_t)row1 * Pd;

    {
        float sn, cs;
        __sincosf(-6.283185307179586f * (float)tid / 1024.0f, &sn, &cs);
        Tw[tid] = make_float2(cs, sn);
    }

    const float inv_scale = 1.0f / 32.0f;

    #pragma unroll
    for (int u = 0; u < 4; u++) {
        int i = tid + u * 256;
        Z[rev4(i)] = make_float2(q0[i], k0[i]);
    }
    __syncthreads();
    fft1024_r4(Z, Tw, tid, false);
    #pragma unroll
    for (int u = 0; u < 4; u++) {
        int i = tid + u * 256;
        float2 zj = Z[i];
        float2 zn = Z[(1024 - i) & 1023];
        float Qx = 0.5f * (zj.x + zn.x), Qy = 0.5f * (zj.y - zn.y);
        float Kxr = 0.5f * (zj.y + zn.y), Kyr = -0.5f * (zj.x - zn.x);
        A0[i] = make_float2((Kxr * Qx + Kyr * Qy) * inv_scale,
                            (Kyr * Qx - Kxr * Qy) * inv_scale);
    }
    __syncthreads();

    #pragma unroll
    for (int u = 0; u < 4; u++) {
        int i = tid + u * 256;
        Z[rev4(i)] = make_float2(q1[i], k1[i]);
    }
    __syncthreads();
    fft1024_r4(Z, Tw, tid, false);
    #pragma unroll
    for (int u = 0; u < 4; u++) {
        int i = tid + u * 256;
        float2 zj = Z[i];
        float2 zn = Z[(1024 - i) & 1023];
        float Qx = 0.5f * (zj.x + zn.x), Qy = 0.5f * (zj.y - zn.y);
        float Kxr = 0.5f * (zj.y + zn.y), Kyr = -0.5f * (zj.x - zn.x);
        A1[i] = make_float2((Kxr * Qx + Kyr * Qy) * inv_scale,
                            (Kyr * Qx - Kxr * Qy) * inv_scale);
    }
    __syncthreads();

    #pragma unroll
    for (int u = 0; u < 4; u++) {
        int i = tid + u * 256;
        Z[rev4(i)] = make_float2(v0[i], v1[i]);
    }
    __syncthreads();
    fft1024_r4(Z, Tw, tid, false);
    #pragma unroll
    for (int u = 0; u < 4; u++) {
        int i = tid + u * 256;
        float2 zj = Z[i];
        float2 zn = Z[(1024 - i) & 1023];
        float2 V0 = make_float2(0.5f * (zj.x + zn.x), 0.5f * (zj.y - zn.y));
        float2 V1 = make_float2(0.5f * (zj.y + zn.y), -0.5f * (zj.x - zn.x));
        A0[i] = cmulf(A0[i], V0);
        A1[i] = cmulf(A1[i], V1);
    }
    __syncthreads();

    #pragma unroll
    for (int u = 0; u < 4; u++) {
        int i = tid + u * 256;
        int ni = (1024 - i) & 1023;
        float2 w0 = A0[i], w0n = A0[ni];
        float2 w1 = A1[i], w1n = A1[ni];
        float2 S0 = make_float2(0.5f * (w0.x + w0n.x), 0.5f * (w0.y - w0n.y));
        float2 S1 = make_float2(0.5f * (w1.x + w1n.x), 0.5f * (w1.y - w1n.y));
        Z[rev4(i)] = make_float2(S0.x - S1.y, S0.y + S1.x);
    }
    __syncthreads();
    fft1024_r4(Z, Tw, tid, true);

    __half* oh0 = Oh + (size_t)row0 * Pd;
    __half* om0 = Om + (size_t)row0 * Pd;
    __half* oh1 = Oh + (size_t)row1 * Pd;
    __half* om1 = Om + (size_t)row1 * Pd;
    const float invN = 1.0f / 1024.0f;
    #pragma unroll
    for (int u = 0; u < 4; u++) {
        int i = tid + u * 256;
        float s0 = Z[i].x * invN;
        float s1 = Z[i].y * invN;
        __half h0, m0, h1, m1;
        split2h(s0, h0, m0);
        split2h(s1, h1, m1);
        oh0[i] = h0; om0[i] = m0;
        oh1[i] = h1; om1[i] = m1;
    }
}

// ---------------- launch ----------------
extern "C" void kernel_launch(void* const* d_in, const int* in_sizes, int n_in,
                              void* d_out, int out_size) {
    (void)in_sizes; (void)n_in; (void)out_size;
    const float* x      = (const float*)d_in[0];
    const float* conv_w = (const float*)d_in[1];
    const float* conv_b = (const float*)d_in[2];
    const float* wq     = (const float*)d_in[3];
    const float* bq     = (const float*)d_in[4];
    const float* wk     = (const float*)d_in[5];
    const float* bk     = (const float*)d_in[6];
    const float* wv     = (const float*)d_in[7];
    const float* bv     = (const float*)d_in[8];
    const float* wo     = (const float*)d_in[9];
    const float* bo     = (const float*)d_in[10];
    float* out = (float*)d_out;

    float *xb, *qkv, *bqkv, *wavg, *bavg;
    __half *ch, *cm, *ph, *pm, *wqkvh, *woh;
    cudaGetSymbolAddress((void**)&xb,    g_x);
    cudaGetSymbolAddress((void**)&ch,    g_ch);
    cudaGetSymbolAddress((void**)&cm,    g_cm);
    cudaGetSymbolAddress((void**)&qkv,   g_qkv);
    cudaGetSymbolAddress((void**)&ph,    g_ph);
    cudaGetSymbolAddress((void**)&pm,    g_pm);
    cudaGetSymbolAddress((void**)&wqkvh, g_wqkv);
    cudaGetSymbolAddress((void**)&woh,   g_wo);
    cudaGetSymbolAddress((void**)&bqkv,  g_bqkv);
    cudaGetSymbolAddress((void**)&wavg,  g_wavg);
    cudaGetSymbolAddress((void**)&bavg,  g_bavg);

    cudaFuncSetAttribute(gemm_mma_kernel,
                         cudaFuncAttributeMaxDynamicSharedMemorySize, GEMM_SMEM);

    const size_t LPW = (size_t)Ld * Pd * Wd;   // 4M elements

    avg_conv_kernel<<<1, 64>>>(conv_w, conv_b, wavg, bavg);

    cvt16_all_kernel<<<2048, 256>>>(wq, wk, wv, wo, wqkvh, woh, (int)(LPW / 8));

    cudaMemcpyAsync(bqkv,               bq, Ld * Pd * 4, cudaMemcpyDeviceToDevice);
    cudaMemcpyAsync(bqkv + Ld * Pd,     bk, Ld * Pd * 4, cudaMemcpyDeviceToDevice);
    cudaMemcpyAsync(bqkv + 2 * Ld * Pd, bv, Ld * Pd * 4, cudaMemcpyDeviceToDevice);

    const size_t RP = (size_t)ROWS * Pd;

    for (int l = 0; l < Ld; l++) {
        const float* xin = (l == 0) ? x : xb;
        float* xout = (l == Ld - 1) ? out : xb;

        conv_row_kernel<<<ROWS, 256>>>(xin, ch, cm, wavg + l * Kc, bavg + l);

        // qkv: ntN=8 (Pd/128), 32 m-tiles, 3 z -> 768 tiles
        gemm_mma_kernel<<<NSLOTS, 256, GEMM_SMEM>>>(
            ch, cm,
            wqkvh + (size_t)l * Pd * Wd,
            bqkv + (size_t)l * Pd, qkv,
            Wd, Pd, LPW, (size_t)Ld * Pd, RP,
            8, 768);

        fft_attn_kernel<<<ROWS / 2, 256>>>(qkv, qkv + RP, qkv + 2 * RP, ph, pm);

        // wo: ntN=16 (Wd/128), 32 m-tiles, 1 z -> 512 tiles
        gemm_mma_kernel<<<NSLOTS, 256, GEMM_SMEM>>>(
            ph, pm,
            woh + (size_t)l * Wd * Pd,
            bo + (size_t)l * Wd, xout,
            Pd, Wd, 0, 0, 0,
            16, 512);
    }
}